// round 10
// baseline (speedup 1.0000x reference)
#include <cuda_runtime.h>
#include <cuda_bf16.h>

// PixCorr: mean over rows of per-row Pearson correlation between
// preds[n,:] and targets[n,:], each row D = 3*256*256 = 196608 fp32.
// Pure HBM-streaming (~402 MB read).
//
// Perfectly balanced static partition: the flat float4 index space
// (256 rows x 49152 = 12,582,912) is split into 296 equal contiguous spans
// (one per block, 148 SMs x 2 = exactly one wave). Spans ignore row
// boundaries; since SPAN < row length, each span covers at most 2 row
// segments. Each segment is one long uninterrupted streaming loop
// (~20-41 iters/thread) followed by a single block reduction -> same
// bubble count as the best measured config, but zero work imbalance.
// Per-(block,segment) partials are deterministic; the last block to
// finish gathers <=3 partials per row (closed-form mapping), computes
// correlations + mean, writes out, resets the counter (graph-replayable).

static constexpr int NROWS   = 256;
static constexpr int D_ELEMS = 3 * 256 * 256;          // 196608
static constexpr int D4      = D_ELEMS / 4;            // 49152 float4 per row
static constexpr int TOTAL4  = NROWS * D4;             // 12,582,912
static constexpr int GRID    = 296;                    // 148 SMs x 2
static constexpr int SPAN    = (TOTAL4 + GRID - 1) / GRID;  // 42511
static constexpr int TPB     = 1024;

// Scratch (device allocation forbidden). g_done reset by elected block.
__device__ float        g_part[GRID * 2 * 5];
__device__ unsigned int g_done;

__global__ void __launch_bounds__(TPB, 2)
pixcorr_balanced_kernel(const float* __restrict__ preds,
                        const float* __restrict__ targets,
                        float* __restrict__ out)
{
    const float4* __restrict__ zbase = reinterpret_cast<const float4*>(targets);
    const float4* __restrict__ bbase = reinterpret_cast<const float4*>(preds);

    const int warp = threadIdx.x >> 5;
    const int lane = threadIdx.x & 31;
    __shared__ float sm[5][32];

    const int b       = blockIdx.x;
    const int g_start = b * SPAN;
    const int g_end   = min(g_start + SPAN, TOTAL4);
    const int r0      = g_start / D4;                  // first row touched
    const int mid     = min(g_end, (r0 + 1) * D4);     // row boundary split

    // Two row segments: [g_start, mid) in row r0, [mid, g_end) in row r0+1.
    #pragma unroll 1
    for (int seg = 0; seg < 2; ++seg) {
        const int s = seg ? mid : g_start;
        const int e = seg ? g_end : mid;

        float sz = 0.f, sb = 0.f, szz = 0.f, sbb = 0.f, szb = 0.f;

        // Long uninterrupted streaming run; unroll so ptxas front-batches
        // the LDG.128s (high MLP -> DRAM latency fully hidden).
        #pragma unroll 4
        for (int i = s + threadIdx.x; i < e; i += TPB) {
            const float4 zv = zbase[i];
            const float4 bv = bbase[i];
            sz  += (zv.x + zv.y) + (zv.z + zv.w);
            sb  += (bv.x + bv.y) + (bv.z + bv.w);
            szz += zv.x * zv.x + zv.y * zv.y + zv.z * zv.z + zv.w * zv.w;
            sbb += bv.x * bv.x + bv.y * bv.y + bv.z * bv.z + bv.w * bv.w;
            szb += zv.x * bv.x + zv.y * bv.y + zv.z * bv.z + zv.w * bv.w;
        }

        // Block reduction of the 5 accumulators.
        #pragma unroll
        for (int o = 16; o > 0; o >>= 1) {
            sz  += __shfl_xor_sync(0xffffffffu, sz,  o);
            sb  += __shfl_xor_sync(0xffffffffu, sb,  o);
            szz += __shfl_xor_sync(0xffffffffu, szz, o);
            sbb += __shfl_xor_sync(0xffffffffu, sbb, o);
            szb += __shfl_xor_sync(0xffffffffu, szb, o);
        }
        if (lane == 0) {
            sm[0][warp] = sz;  sm[1][warp] = sb;  sm[2][warp] = szz;
            sm[3][warp] = sbb; sm[4][warp] = szb;
        }
        __syncthreads();
        if (warp == 0) {
            sz  = sm[0][lane]; sb  = sm[1][lane]; szz = sm[2][lane];
            sbb = sm[3][lane]; szb = sm[4][lane];
            #pragma unroll
            for (int o = 16; o > 0; o >>= 1) {
                sz  += __shfl_xor_sync(0xffffffffu, sz,  o);
                sb  += __shfl_xor_sync(0xffffffffu, sb,  o);
                szz += __shfl_xor_sync(0xffffffffu, szz, o);
                sbb += __shfl_xor_sync(0xffffffffu, sbb, o);
                szb += __shfl_xor_sync(0xffffffffu, szb, o);
            }
            if (lane == 0) {
                float* p = &g_part[(b * 2 + seg) * 5];
                p[0] = sz; p[1] = sb; p[2] = szz; p[3] = sbb; p[4] = szb;
            }
        }
        __syncthreads();       // sm[] reusable by next segment
    }

    // ── Last-block-done election ──────────────────────────────────────────
    __shared__ bool is_last;
    if (threadIdx.x == 0) {
        __threadfence();       // publish g_part writes GPU-wide
        unsigned int old = atomicAdd(&g_done, 1u);
        is_last = (old == GRID - 1);
    }
    __syncthreads();
    if (!is_last) return;

    // ── Final stage: threads 0..255 each own one row ──────────────────────
    float corr = 0.f;
    if (threadIdx.x < NROWS) {
        const int r = threadIdx.x;
        // Blocks whose span intersects row r's range [r*D4, (r+1)*D4):
        const int bl = (r * D4) / SPAN;
        const int bh = ((r + 1) * D4 - 1) / SPAN;
        float tsz = 0.f, tsb = 0.f, tszz = 0.f, tsbb = 0.f, tszb = 0.f;
        for (int bb = bl; bb <= bh; ++bb) {
            const int r0b = (bb * SPAN) / D4;          // block bb's first row
            const int seg = (r == r0b) ? 0 : 1;
            const float* p = &g_part[(bb * 2 + seg) * 5];
            tsz += p[0]; tsb += p[1]; tszz += p[2]; tsbb += p[3]; tszb += p[4];
        }
        const float invD = 1.0f / (float)D_ELEMS;
        const float num  = tszb - tsz * tsb * invD;
        const float vz   = fmaxf(tszz - tsz * tsz * invD, 0.0f);
        const float vb   = fmaxf(tsbb - tsb * tsb * invD, 0.0f);
        const float den  = sqrtf(vz) * sqrtf(vb) + 1e-6f;
        corr = num / den;
    }

    // Mean over 256 rows (warps 0..7 hold the values).
    #pragma unroll
    for (int o = 16; o > 0; o >>= 1)
        corr += __shfl_xor_sync(0xffffffffu, corr, o);
    if (lane == 0) sm[0][warp] = corr;
    __syncthreads();
    if (threadIdx.x < 8) {
        float v = sm[0][threadIdx.x];
        #pragma unroll
        for (int o = 4; o > 0; o >>= 1)
            v += __shfl_xor_sync(0x000000ffu, v, o);
        if (threadIdx.x == 0) {
            out[0] = v * (1.0f / (float)NROWS);
            g_done = 0;        // reset for next graph replay
        }
    }
}

extern "C" void kernel_launch(void* const* d_in, const int* in_sizes, int n_in,
                              void* d_out, int out_size)
{
    const float* preds   = (const float*)d_in[0];
    const float* targets = (const float*)d_in[1];
    float* out = (float*)d_out;

    pixcorr_balanced_kernel<<<GRID, TPB>>>(preds, targets, out);
}

// round 11
// speedup vs baseline: 1.0817x; 1.0817x over previous
#include <cuda_runtime.h>
#include <cuda_bf16.h>

// PixCorr: mean over rows of per-row Pearson correlation between
// preds[n,:] and targets[n,:], each row D = 3*256*256 = 196608 fp32.
// Pure HBM-streaming (~402 MB read, ceiling ~6.75 TB/s measured).
//
// Structure: EXACTLY the R2 streaming kernel (256 blocks x 1024 threads,
// one row per block, compile-time 48-iteration float4 loop -- the only
// configuration measured to saturate HBM at 6.74 TB/s), with the former
// second kernel fused in as a last-block-done epilogue (saves the measured
// 4.35us second-launch cost). Per-row results are deterministic; the
// election counter self-resets so the kernel is graph-replayable.

static constexpr int NROWS   = 256;
static constexpr int D_ELEMS = 3 * 256 * 256;       // 196608
static constexpr int D4      = D_ELEMS / 4;         // 49152 float4 per row
static constexpr int TPB     = 1024;                // 48 iters/thread

// Scratch (device allocation forbidden). g_done is reset by the elected
// last block at the end of every call.
__device__ float        g_corr[NROWS];
__device__ unsigned int g_done;

__global__ void __launch_bounds__(TPB, 2)
pixcorr_fused_kernel(const float* __restrict__ preds,
                     const float* __restrict__ targets,
                     float* __restrict__ out)
{
    const int row = blockIdx.x;
    const float4* __restrict__ zp =
        reinterpret_cast<const float4*>(targets) + (size_t)row * D4;
    const float4* __restrict__ bp =
        reinterpret_cast<const float4*>(preds) + (size_t)row * D4;

    float sz = 0.f, sb = 0.f, szz = 0.f, sbb = 0.f, szb = 0.f;

    // 48 iterations per thread, compile-time trip count; unroll 4 so ptxas
    // front-batches the LDG.128s (high MLP -> DRAM latency fully hidden).
    #pragma unroll 4
    for (int i = threadIdx.x; i < D4; i += TPB) {
        const float4 zv = zp[i];
        const float4 bv = bp[i];
        sz  += (zv.x + zv.y) + (zv.z + zv.w);
        sb  += (bv.x + bv.y) + (bv.z + bv.w);
        szz += zv.x * zv.x + zv.y * zv.y + zv.z * zv.z + zv.w * zv.w;
        sbb += bv.x * bv.x + bv.y * bv.y + bv.z * bv.z + bv.w * bv.w;
        szb += zv.x * bv.x + zv.y * bv.y + zv.z * bv.z + zv.w * bv.w;
    }

    // Warp-level reduction of all 5 accumulators.
    #pragma unroll
    for (int o = 16; o > 0; o >>= 1) {
        sz  += __shfl_xor_sync(0xffffffffu, sz,  o);
        sb  += __shfl_xor_sync(0xffffffffu, sb,  o);
        szz += __shfl_xor_sync(0xffffffffu, szz, o);
        sbb += __shfl_xor_sync(0xffffffffu, sbb, o);
        szb += __shfl_xor_sync(0xffffffffu, szb, o);
    }

    __shared__ float sm[5][32];
    const int warp = threadIdx.x >> 5;
    const int lane = threadIdx.x & 31;
    if (lane == 0) {
        sm[0][warp] = sz;
        sm[1][warp] = sb;
        sm[2][warp] = szz;
        sm[3][warp] = sbb;
        sm[4][warp] = szb;
    }
    __syncthreads();

    if (warp == 0) {
        sz  = sm[0][lane];
        sb  = sm[1][lane];
        szz = sm[2][lane];
        sbb = sm[3][lane];
        szb = sm[4][lane];
        #pragma unroll
        for (int o = 16; o > 0; o >>= 1) {
            sz  += __shfl_xor_sync(0xffffffffu, sz,  o);
            sb  += __shfl_xor_sync(0xffffffffu, sb,  o);
            szz += __shfl_xor_sync(0xffffffffu, szz, o);
            sbb += __shfl_xor_sync(0xffffffffu, sbb, o);
            szb += __shfl_xor_sync(0xffffffffu, szb, o);
        }
        if (lane == 0) {
            const float invD = 1.0f / (float)D_ELEMS;
            const float num  = szb - sz * sb * invD;
            const float vz   = fmaxf(szz - sz * sz * invD, 0.0f);
            const float vb   = fmaxf(sbb - sb * sb * invD, 0.0f);
            const float den  = sqrtf(vz) * sqrtf(vb) + 1e-6f;
            g_corr[row] = num / den;
        }
    }

    // ── Last-block-done election (replaces the second kernel launch) ──────
    __shared__ bool is_last;
    __syncthreads();                     // g_corr store issued block-wide
    if (threadIdx.x == 0) {
        __threadfence();                 // publish g_corr[row] GPU-wide
        unsigned int old = atomicAdd(&g_done, 1u);
        is_last = (old == NROWS - 1);
    }
    __syncthreads();
    if (!is_last) return;

    // ── Final mean over 256 rows (L2-resident reads; ~0.5us) ──────────────
    {
        float v = (threadIdx.x < NROWS) ? g_corr[threadIdx.x] : 0.0f;
        #pragma unroll
        for (int o = 16; o > 0; o >>= 1)
            v += __shfl_xor_sync(0xffffffffu, v, o);
        if (lane == 0) sm[0][warp] = v;
        __syncthreads();
        if (threadIdx.x < 8) {
            float t = sm[0][threadIdx.x];
            #pragma unroll
            for (int o = 4; o > 0; o >>= 1)
                t += __shfl_xor_sync(0x000000ffu, t, o);
            if (threadIdx.x == 0) {
                out[0] = t * (1.0f / (float)NROWS);
                g_done = 0;              // reset for next graph replay
            }
        }
    }
}

extern "C" void kernel_launch(void* const* d_in, const int* in_sizes, int n_in,
                              void* d_out, int out_size)
{
    const float* preds   = (const float*)d_in[0];
    const float* targets = (const float*)d_in[1];
    float* out = (float*)d_out;

    pixcorr_fused_kernel<<<NROWS, TPB>>>(preds, targets, out);
}